// round 2
// baseline (speedup 1.0000x reference)
#include <cuda_runtime.h>
#include <cuda_bf16.h>
#include <math.h>

#define S      64
#define S2     4096
#define RF     15
#define RFP    225
#define INPUT  48
#define WR     14
#define WW     29
#define WN     841
#define ITERS  50

#define TE (1.5f/4096.0f)
#define TI (1.0f/4096.0f)

// -------- device scratch --------
// Tiled bf16 dense weights: index ((g*64 + t)*32 + lane), g = rowgroup*8 + warpchunk
// uint4 = 8 bf16 = cols [w*512 + t*8 .. +8) of row (b*32 + lane)
__device__ uint4          g_w2t[1024 * 64 * 32];   // 32 MB
__device__ __nv_bfloat16  g_l4wh[(size_t)S2 * WN]; // 6.9 MB windowed (lwe - mid)
__device__ float g_aff[S2];
__device__ float g_smid[S2];
__device__ float g_sexc[S2];
__device__ float g_sinh[S2];
__device__ float g_cur[2][S2];
__device__ float g_l4[2][S2];

// ---------------------------------------------------------------------------
// K_sums: per-row normalization sums (also warms lc into L2 for K_build2).
// ---------------------------------------------------------------------------
__global__ void K_sums(const float* __restrict__ lc, const float* __restrict__ l4c) {
    int row = blockIdx.x;
    int tid = threadIdx.x;
    int y = row >> 6, x = row & 63;

    float se = 0.f, si = 0.f, sm = 0.f;
    const float* lcrow = lc + (size_t)row * S2;
    for (int j = tid; j < S2; j += 256) {
        float v = lcrow[j];
        se += fmaxf(v - TE, 0.f);
        si += fmaxf(v - TI, 0.f);
    }
    const float* l4crow = l4c + (size_t)row * S2;
    for (int k = tid; k < WN; k += 256) {
        int dy = k / WW - WR;
        int dx = k % WW - WR;
        int yy = y + dy, xx = x + dx;
        int d2 = dy * dy + dx * dx;
        if (d2 <= 156 && (unsigned)yy < S && (unsigned)xx < S)
            sm += l4crow[yy * S + xx];
    }
    __shared__ float red[3][8];
    for (int o = 16; o; o >>= 1) {
        se += __shfl_down_sync(0xffffffffu, se, o);
        si += __shfl_down_sync(0xffffffffu, si, o);
        sm += __shfl_down_sync(0xffffffffu, sm, o);
    }
    int w = tid >> 5, lane = tid & 31;
    if (lane == 0) { red[0][w] = se; red[1][w] = si; red[2][w] = sm; }
    __syncthreads();
    if (tid == 0) {
        float a = 0, b = 0, c = 0;
        for (int i = 0; i < 8; i++) { a += red[0][i]; b += red[1][i]; c += red[2][i]; }
        g_sexc[row] = a; g_sinh[row] = b; g_smid[row] = c;
    }
}

// ---------------------------------------------------------------------------
// K_build2: materialize transposed-tiled bf16 W2. grid = 1024 (one g-chunk each).
// Writes fully coalesced; reads are 32B sectors (L2-hot after K_sums).
// ---------------------------------------------------------------------------
__global__ void K_build2(const float* __restrict__ lc) {
    int g = blockIdx.x;
    int b = g >> 3, w = g & 7;
    for (int task = threadIdx.x; task < 64 * 32; task += 256) {
        int t = task >> 5, lane = task & 31;
        int row = b * 32 + lane;
        int col = w * 512 + t * 8;
        const float* p = lc + (size_t)row * S2 + col;
        float inv_e = 1.f / (g_sexc[row] + 1e-11f);
        float inv_i = 1.f / (g_sinh[row] + 1e-11f);
        float4 a = *(const float4*)p;
        float4 c = *(const float4*)(p + 4);
        float v[8] = {a.x, a.y, a.z, a.w, c.x, c.y, c.z, c.w};
        __nv_bfloat162 h[4];
#pragma unroll
        for (int e = 0; e < 4; e++) {
            float w0 = fmaxf(v[2*e]   - TE, 0.f) * inv_e - fmaxf(v[2*e]   - TI, 0.f) * inv_i;
            float w1 = fmaxf(v[2*e+1] - TE, 0.f) * inv_e - fmaxf(v[2*e+1] - TI, 0.f) * inv_i;
            h[e] = __floats2bfloat162_rn(w0, w1);
        }
        g_w2t[((size_t)g * 64 + t) * 32 + lane] = *(uint4*)h;
    }
}

// ---------------------------------------------------------------------------
// K_buildw: windowed bf16 l4w = lwe - normalized circle-masked l4c. grid = S2.
// ---------------------------------------------------------------------------
__global__ void K_buildw(const float* __restrict__ l4c, const float* __restrict__ lwe) {
    int row = blockIdx.x;
    int tid = threadIdx.x;
    int y = row >> 6, x = row & 63;
    float inv_m = 1.f / (g_smid[row] + 1e-11f);
    const float* l4crow = l4c + (size_t)row * S2;
    const float* lwerow = lwe + (size_t)row * S2;
    __nv_bfloat16* wrow = g_l4wh + (size_t)row * WN;
    for (int k = tid; k < WN; k += 256) {
        int dy = k / WW - WR;
        int dx = k % WW - WR;
        int yy = y + dy, xx = x + dx;
        float wv = 0.f;
        if ((unsigned)yy < S && (unsigned)xx < S) {
            int j = yy * S + xx;
            int d2 = dy * dy + dx * dx;
            float mid = (d2 <= 156) ? l4crow[j] * inv_m : 0.f;
            wv = lwerow[j] - mid;
        }
        wrow[k] = __float2bfloat16(wv);   // OOB exactly 0 -> branchless gather
    }
}

// ---------------------------------------------------------------------------
// K_aff: afferent drive per unit (one warp per unit).
// ---------------------------------------------------------------------------
__global__ void K_aff(const float* __restrict__ img, const int* __restrict__ grids,
                      const float* __restrict__ affw) {
    int unit = blockIdx.x * 8 + (threadIdx.x >> 5);
    int lane = threadIdx.x & 31;
    float a = 0.f;
    const int* g = grids + (size_t)unit * RFP * 2;
    const float* w = affw + (size_t)unit * RFP;
    for (int p = lane; p < RFP; p += 32) {
        a += img[g[p * 2 + 0] * INPUT + g[p * 2 + 1]] * w[p];
    }
    for (int o = 16; o; o >>= 1) a += __shfl_down_sync(0xffffffffu, a, o);
    if (lane == 0) g_aff[unit] = a;
}

__global__ void K_init() {
    int i = blockIdx.x * blockDim.x + threadIdx.x;
    if (i < S2) { g_cur[0][i] = 0.f; g_l4[0][i] = 0.f; }
}

// ---------------------------------------------------------------------------
// K_iter: one settling step. grid = 128 blocks x 256 threads.
// Block b owns rows [b*32, b*32+32). Dense part: split-K, warp w covers cols
// [w*512, w*512+512), thread = row within group, x is smem broadcast.
// ---------------------------------------------------------------------------
__global__ void __launch_bounds__(256) K_iter(int src, int dst,
                                              const float* __restrict__ thr,
                                              const float* __restrict__ l4thr,
                                              float* __restrict__ out, int last) {
    __shared__ float4 scur4[S2 / 4];   // 16 KB
    __shared__ float  sl4[S2];         // 16 KB
    __shared__ float  red[8][32];
    __shared__ float  swin[32];
    float* scur = (float*)scur4;
    int tid = threadIdx.x;

    // stage state vectors
    {
        const float4* c4  = (const float4*)g_cur[src];
        const float4* l4p = (const float4*)g_l4[src];
        float4* sl = (float4*)sl4;
        for (int i = tid; i < S2 / 4; i += 256) { scur4[i] = c4[i]; sl[i] = l4p[i]; }
    }
    __syncthreads();

    int warp = tid >> 5, lane = tid & 31;

    // ---- dense: W2 @ cur, transposed-tiled bf16, f32 accumulate ----
    {
        int g = blockIdx.x * 8 + warp;
        const uint4* wp = g_w2t + (size_t)g * (64 * 32);
        float acc = 0.f;
#pragma unroll 8
        for (int t = 0; t < 64; t++) {
            uint4 wv = wp[t * 32 + lane];
            float4 xa = scur4[warp * 128 + 2 * t];
            float4 xb = scur4[warp * 128 + 2 * t + 1];
            float2 f0 = __bfloat1622float2(*reinterpret_cast<__nv_bfloat162*>(&wv.x));
            float2 f1 = __bfloat1622float2(*reinterpret_cast<__nv_bfloat162*>(&wv.y));
            float2 f2 = __bfloat1622float2(*reinterpret_cast<__nv_bfloat162*>(&wv.z));
            float2 f3 = __bfloat1622float2(*reinterpret_cast<__nv_bfloat162*>(&wv.w));
            acc = fmaf(f0.x, xa.x, acc); acc = fmaf(f0.y, xa.y, acc);
            acc = fmaf(f1.x, xa.z, acc); acc = fmaf(f1.y, xa.w, acc);
            acc = fmaf(f2.x, xb.x, acc); acc = fmaf(f2.y, xb.y, acc);
            acc = fmaf(f3.x, xb.z, acc); acc = fmaf(f3.y, xb.w, acc);
        }
        red[warp][lane] = acc;
    }
    __syncthreads();

    // ---- windowed: l4w @ l4 (warp per row, 4 rows per warp) ----
    for (int q = 0; q < 4; q++) {
        int rl = warp * 4 + q;
        int row = blockIdx.x * 32 + rl;
        int y = row >> 6, x = row & 63;
        const __nv_bfloat16* lw = g_l4wh + (size_t)row * WN;
        float a = 0.f;
#pragma unroll 4
        for (int k = lane; k < WN; k += 32) {
            int dy = k / WW - WR;
            int dx = k % WW - WR;
            int yy = min(max(y + dy, 0), S - 1);
            int xx = min(max(x + dx, 0), S - 1);
            a += __bfloat162float(lw[k]) * sl4[yy * S + xx];
        }
        for (int o = 16; o; o >>= 1) a += __shfl_down_sync(0xffffffffu, a, o);
        if (lane == 0) swin[rl] = a;
    }
    __syncthreads();

    // ---- final assembly: warp 0, one lane per row ----
    if (warp == 0) {
        int row = blockIdx.x * 32 + lane;
        float d = 0.f;
#pragma unroll
        for (int w = 0; w < 8; w++) d += red[w][lane];
        // b = 0.5/(0.5+1e-11) == 1.0f exactly in f32
        float l4_aff = 0.5f * (g_aff[row] + scur[row]);
        float l4n = tanhf(fmaxf(l4_aff + swin[lane] - l4thr[row], 0.f) * 2.0f);
        float curn = tanhf(fmaxf(l4n + d - thr[row], 0.f));
        g_l4[dst][row] = l4n;
        g_cur[dst][row] = curn;
        if (last) out[row] = curn;
    }
}

// ---------------------------------------------------------------------------
extern "C" void kernel_launch(void* const* d_in, const int* in_sizes, int n_in,
                              void* d_out, int out_size) {
    const float* img   = (const float*)d_in[0];
    const int*   grids = (const int*)d_in[1];
    const float* affw  = (const float*)d_in[2];
    const float* lc    = (const float*)d_in[3];
    const float* l4c   = (const float*)d_in[4];
    const float* lwe   = (const float*)d_in[5];
    const float* thr   = (const float*)d_in[7];
    const float* l4thr = (const float*)d_in[8];
    float* out = (float*)d_out;

    K_sums<<<S2, 256>>>(lc, l4c);
    K_build2<<<1024, 256>>>(lc);
    K_buildw<<<S2, 256>>>(l4c, lwe);
    K_aff<<<S2 / 8, 256>>>(img, grids, affw);
    K_init<<<(S2 + 255) / 256, 256>>>();

    for (int i = 0; i < ITERS; i++) {
        K_iter<<<128, 256>>>(i & 1, (i + 1) & 1, thr, l4thr, out, i == ITERS - 1);
    }
}

// round 3
// speedup vs baseline: 1.0216x; 1.0216x over previous
#include <cuda_runtime.h>
#include <cuda_bf16.h>
#include <math.h>

#define S      64
#define S2     4096
#define RF     15
#define RFP    225
#define INPUT  48
#define WR     14
#define WW     29
#define WN     841
#define ITERS  50
#define NBLK   128          // persistent grid: must be <= SM count (148)

#define TE (1.5f/4096.0f)
#define TI (1.0f/4096.0f)

// -------- device scratch --------
// Tiled bf16 dense weights: index ((g*64 + t)*32 + lane), g = rowgroup*8 + warpchunk
// uint4 = 8 bf16 = cols [w*512 + t*8 .. +8) of row (b*32 + lane)
__device__ uint4          g_w2t[1024 * 64 * 32];   // 32 MB
__device__ __nv_bfloat16  g_l4wh[(size_t)S2 * WN]; // 6.9 MB windowed (lwe - mid)
__device__ float g_aff[S2];
__device__ float g_smid[S2];
__device__ float g_sexc[S2];
__device__ float g_sinh[S2];
__device__ float g_cur[2][S2];
__device__ float g_l4[2][S2];
__device__ unsigned g_bar;

// ---------------------------------------------------------------------------
// K_sums: per-row normalization sums (also warms lc into L2 for K_build2).
// ---------------------------------------------------------------------------
__global__ void K_sums(const float* __restrict__ lc, const float* __restrict__ l4c) {
    int row = blockIdx.x;
    int tid = threadIdx.x;
    int y = row >> 6, x = row & 63;

    float se = 0.f, si = 0.f, sm = 0.f;
    const float* lcrow = lc + (size_t)row * S2;
    for (int j = tid; j < S2; j += 256) {
        float v = lcrow[j];
        se += fmaxf(v - TE, 0.f);
        si += fmaxf(v - TI, 0.f);
    }
    const float* l4crow = l4c + (size_t)row * S2;
    for (int k = tid; k < WN; k += 256) {
        int dy = k / WW - WR;
        int dx = k % WW - WR;
        int yy = y + dy, xx = x + dx;
        int d2 = dy * dy + dx * dx;
        if (d2 <= 156 && (unsigned)yy < S && (unsigned)xx < S)
            sm += l4crow[yy * S + xx];
    }
    __shared__ float red[3][8];
    for (int o = 16; o; o >>= 1) {
        se += __shfl_down_sync(0xffffffffu, se, o);
        si += __shfl_down_sync(0xffffffffu, si, o);
        sm += __shfl_down_sync(0xffffffffu, sm, o);
    }
    int w = tid >> 5, lane = tid & 31;
    if (lane == 0) { red[0][w] = se; red[1][w] = si; red[2][w] = sm; }
    __syncthreads();
    if (tid == 0) {
        float a = 0, b = 0, c = 0;
        for (int i = 0; i < 8; i++) { a += red[0][i]; b += red[1][i]; c += red[2][i]; }
        g_sexc[row] = a; g_sinh[row] = b; g_smid[row] = c;
    }
}

// ---------------------------------------------------------------------------
// K_build2: materialize transposed-tiled bf16 W2. grid = 1024.
// ---------------------------------------------------------------------------
__global__ void K_build2(const float* __restrict__ lc) {
    int g = blockIdx.x;
    int b = g >> 3, w = g & 7;
    for (int task = threadIdx.x; task < 64 * 32; task += 256) {
        int t = task >> 5, lane = task & 31;
        int row = b * 32 + lane;
        int col = w * 512 + t * 8;
        const float* p = lc + (size_t)row * S2 + col;
        float inv_e = 1.f / (g_sexc[row] + 1e-11f);
        float inv_i = 1.f / (g_sinh[row] + 1e-11f);
        float4 a = *(const float4*)p;
        float4 c = *(const float4*)(p + 4);
        float v[8] = {a.x, a.y, a.z, a.w, c.x, c.y, c.z, c.w};
        __nv_bfloat162 h[4];
#pragma unroll
        for (int e = 0; e < 4; e++) {
            float w0 = fmaxf(v[2*e]   - TE, 0.f) * inv_e - fmaxf(v[2*e]   - TI, 0.f) * inv_i;
            float w1 = fmaxf(v[2*e+1] - TE, 0.f) * inv_e - fmaxf(v[2*e+1] - TI, 0.f) * inv_i;
            h[e] = __floats2bfloat162_rn(w0, w1);
        }
        g_w2t[((size_t)g * 64 + t) * 32 + lane] = *(uint4*)h;
    }
}

// ---------------------------------------------------------------------------
// K_buildw: windowed bf16 l4w = lwe - normalized circle-masked l4c. grid = S2.
// ---------------------------------------------------------------------------
__global__ void K_buildw(const float* __restrict__ l4c, const float* __restrict__ lwe) {
    int row = blockIdx.x;
    int tid = threadIdx.x;
    int y = row >> 6, x = row & 63;
    float inv_m = 1.f / (g_smid[row] + 1e-11f);
    const float* l4crow = l4c + (size_t)row * S2;
    const float* lwerow = lwe + (size_t)row * S2;
    __nv_bfloat16* wrow = g_l4wh + (size_t)row * WN;
    for (int k = tid; k < WN; k += 256) {
        int dy = k / WW - WR;
        int dx = k % WW - WR;
        int yy = y + dy, xx = x + dx;
        float wv = 0.f;
        if ((unsigned)yy < S && (unsigned)xx < S) {
            int j = yy * S + xx;
            int d2 = dy * dy + dx * dx;
            float mid = (d2 <= 156) ? l4crow[j] * inv_m : 0.f;
            wv = lwerow[j] - mid;
        }
        wrow[k] = __float2bfloat16(wv);
    }
}

// ---------------------------------------------------------------------------
// K_aff: afferent drive per unit (one warp per unit).
// ---------------------------------------------------------------------------
__global__ void K_aff(const float* __restrict__ img, const int* __restrict__ grids,
                      const float* __restrict__ affw) {
    int unit = blockIdx.x * 8 + (threadIdx.x >> 5);
    int lane = threadIdx.x & 31;
    float a = 0.f;
    const int* g = grids + (size_t)unit * RFP * 2;
    const float* w = affw + (size_t)unit * RFP;
    for (int p = lane; p < RFP; p += 32) {
        a += img[g[p * 2 + 0] * INPUT + g[p * 2 + 1]] * w[p];
    }
    for (int o = 16; o; o >>= 1) a += __shfl_down_sync(0xffffffffu, a, o);
    if (lane == 0) g_aff[unit] = a;
}

__global__ void K_init() {
    int i = blockIdx.x * blockDim.x + threadIdx.x;
    if (i < S2) { g_cur[0][i] = 0.f; g_l4[0][i] = 0.f; }
    if (i == 0) g_bar = 0u;       // reset grid barrier every replay
}

// ---------------------------------------------------------------------------
// K_persist: ALL 50 settling steps in one launch. grid = NBLK x 256.
// Block b owns rows [b*32, b*32+32). Software grid barrier between steps.
// ---------------------------------------------------------------------------
__global__ void __launch_bounds__(256) K_persist(const float* __restrict__ thr,
                                                 const float* __restrict__ l4thr,
                                                 float* __restrict__ out) {
    __shared__ float4 scur4[S2 / 4];   // 16 KB
    __shared__ float  sl4[S2];         // 16 KB
    __shared__ float  red[8][32];
    __shared__ float  swin[32];
    float* scur = (float*)scur4;
    int tid  = threadIdx.x;
    int warp = tid >> 5, lane = tid & 31;

    for (int it = 0; it < ITERS; it++) {
        int src = it & 1, dst = src ^ 1;

        // ---- stage state vectors into smem ----
        {
            const float4* c4  = (const float4*)g_cur[src];
            const float4* l4p = (const float4*)g_l4[src];
            float4* sl = (float4*)sl4;
            for (int i = tid; i < S2 / 4; i += 256) { scur4[i] = c4[i]; sl[i] = l4p[i]; }
        }
        __syncthreads();

        // ---- dense: W2 @ cur, split-K (warp w covers cols [w*512, +512)) ----
        {
            int g = blockIdx.x * 8 + warp;
            const uint4* wp = g_w2t + (size_t)g * (64 * 32);
            float acc = 0.f;
#pragma unroll 8
            for (int t = 0; t < 64; t++) {
                uint4 wv = wp[t * 32 + lane];
                float4 xa = scur4[warp * 128 + 2 * t];
                float4 xb = scur4[warp * 128 + 2 * t + 1];
                float2 f0 = __bfloat1622float2(*reinterpret_cast<__nv_bfloat162*>(&wv.x));
                float2 f1 = __bfloat1622float2(*reinterpret_cast<__nv_bfloat162*>(&wv.y));
                float2 f2 = __bfloat1622float2(*reinterpret_cast<__nv_bfloat162*>(&wv.z));
                float2 f3 = __bfloat1622float2(*reinterpret_cast<__nv_bfloat162*>(&wv.w));
                acc = fmaf(f0.x, xa.x, acc); acc = fmaf(f0.y, xa.y, acc);
                acc = fmaf(f1.x, xa.z, acc); acc = fmaf(f1.y, xa.w, acc);
                acc = fmaf(f2.x, xb.x, acc); acc = fmaf(f2.y, xb.y, acc);
                acc = fmaf(f3.x, xb.z, acc); acc = fmaf(f3.y, xb.w, acc);
            }
            red[warp][lane] = acc;
        }

        // ---- windowed: l4w @ l4 (warp per row, 4 rows per warp) ----
        for (int q = 0; q < 4; q++) {
            int rl = warp * 4 + q;
            int row = blockIdx.x * 32 + rl;
            int y = row >> 6, x = row & 63;
            const __nv_bfloat16* lw = g_l4wh + (size_t)row * WN;
            float a = 0.f;
#pragma unroll 4
            for (int k = lane; k < WN; k += 32) {
                int dy = k / WW - WR;
                int dx = k % WW - WR;
                int yy = min(max(y + dy, 0), S - 1);
                int xx = min(max(x + dx, 0), S - 1);
                a += __bfloat162float(lw[k]) * sl4[yy * S + xx];
            }
            for (int o = 16; o; o >>= 1) a += __shfl_down_sync(0xffffffffu, a, o);
            if (lane == 0) swin[rl] = a;
        }
        __syncthreads();

        // ---- final assembly: warp 0, one lane per row ----
        if (warp == 0) {
            int row = blockIdx.x * 32 + lane;
            float d = 0.f;
#pragma unroll
            for (int w = 0; w < 8; w++) d += red[w][lane];
            float l4_aff = 0.5f * (g_aff[row] + scur[row]);  // b == 1.0f exactly
            float l4n = tanhf(fmaxf(l4_aff + swin[lane] - l4thr[row], 0.f) * 2.0f);
            float curn = tanhf(fmaxf(l4n + d - thr[row], 0.f));
            g_l4[dst][row] = l4n;
            g_cur[dst][row] = curn;
            if (it == ITERS - 1) out[row] = curn;
        }

        // ---- grid barrier (release: fence-all -> sync -> arrive; acquire: spin -> fence) ----
        __threadfence();
        __syncthreads();
        if (tid == 0) {
            atomicAdd(&g_bar, 1u);
            unsigned target = (unsigned)(it + 1) * gridDim.x;
            while (*(volatile unsigned*)&g_bar < target) { }
            __threadfence();
        }
        __syncthreads();
    }
}

// ---------------------------------------------------------------------------
extern "C" void kernel_launch(void* const* d_in, const int* in_sizes, int n_in,
                              void* d_out, int out_size) {
    const float* img   = (const float*)d_in[0];
    const int*   grids = (const int*)d_in[1];
    const float* affw  = (const float*)d_in[2];
    const float* lc    = (const float*)d_in[3];
    const float* l4c   = (const float*)d_in[4];
    const float* lwe   = (const float*)d_in[5];
    const float* thr   = (const float*)d_in[7];
    const float* l4thr = (const float*)d_in[8];
    float* out = (float*)d_out;

    K_sums<<<S2, 256>>>(lc, l4c);
    K_build2<<<1024, 256>>>(lc);
    K_buildw<<<S2, 256>>>(l4c, lwe);
    K_aff<<<S2 / 8, 256>>>(img, grids, affw);
    K_init<<<(S2 + 255) / 256, 256>>>();
    K_persist<<<NBLK, 256>>>(thr, l4thr, out);
}

// round 4
// speedup vs baseline: 1.5316x; 1.4992x over previous
#include <cuda_runtime.h>
#include <cuda_bf16.h>
#include <math.h>

#define S      64
#define S2     4096
#define RF     15
#define RFP    225
#define INPUT  48
#define WR     14
#define WW     29
#define WN     841
#define ITERS  50
#define NBLK   128          // persistent grid (co-resident: 1 block/SM, 148 SMs)
#define NTHR   512          // 16 warps/block -> 2048 warps, MLP-rich

#define TE (1.5f/4096.0f)
#define TI (1.0f/4096.0f)

// -------- device scratch --------
// Tiled bf16 dense weights: uint4 at [b:128][w:16][t:32][lane:32]
//   = 8 bf16 weights of row (b*32+lane), cols (w*256 + t*8 .. +8)
__device__ uint4          g_w2t[128 * 16 * 32 * 32];   // 32 MB
__device__ __nv_bfloat16  g_l4wh[(size_t)S2 * WN];     // 6.9 MB windowed (lwe - mid)
__device__ float g_aff[S2];
__device__ float g_smid[S2];
__device__ float g_sexc[S2];
__device__ float g_sinh[S2];
__device__ float g_cur[2][S2];
__device__ float g_l4[2][S2];
__device__ unsigned g_bar;

// ---------------------------------------------------------------------------
// K_sums: per-row normalization sums (also warms lc into L2 for K_build2).
// ---------------------------------------------------------------------------
__global__ void K_sums(const float* __restrict__ lc, const float* __restrict__ l4c) {
    int row = blockIdx.x;
    int tid = threadIdx.x;
    int y = row >> 6, x = row & 63;

    float se = 0.f, si = 0.f, sm = 0.f;
    const float* lcrow = lc + (size_t)row * S2;
    for (int j = tid; j < S2; j += 256) {
        float v = lcrow[j];
        se += fmaxf(v - TE, 0.f);
        si += fmaxf(v - TI, 0.f);
    }
    const float* l4crow = l4c + (size_t)row * S2;
    for (int k = tid; k < WN; k += 256) {
        int dy = k / WW - WR;
        int dx = k % WW - WR;
        int yy = y + dy, xx = x + dx;
        int d2 = dy * dy + dx * dx;
        if (d2 <= 156 && (unsigned)yy < S && (unsigned)xx < S)
            sm += l4crow[yy * S + xx];
    }
    __shared__ float red[3][8];
    for (int o = 16; o; o >>= 1) {
        se += __shfl_down_sync(0xffffffffu, se, o);
        si += __shfl_down_sync(0xffffffffu, si, o);
        sm += __shfl_down_sync(0xffffffffu, sm, o);
    }
    int w = tid >> 5, lane = tid & 31;
    if (lane == 0) { red[0][w] = se; red[1][w] = si; red[2][w] = sm; }
    __syncthreads();
    if (tid == 0) {
        float a = 0, b = 0, c = 0;
        for (int i = 0; i < 8; i++) { a += red[0][i]; b += red[1][i]; c += red[2][i]; }
        g_sexc[row] = a; g_sinh[row] = b; g_smid[row] = c;
    }
}

// ---------------------------------------------------------------------------
// K_build2: materialize transposed-tiled bf16 W2. grid = 128*16 = 2048.
// ---------------------------------------------------------------------------
__global__ void K_build2(const float* __restrict__ lc) {
    int b = blockIdx.x >> 4;
    int w = blockIdx.x & 15;
    for (int task = threadIdx.x; task < 32 * 32; task += 256) {
        int t = task >> 5, lane = task & 31;
        int row = b * 32 + lane;
        int col = w * 256 + t * 8;
        const float* p = lc + (size_t)row * S2 + col;
        float inv_e = 1.f / (g_sexc[row] + 1e-11f);
        float inv_i = 1.f / (g_sinh[row] + 1e-11f);
        float4 a = *(const float4*)p;
        float4 c = *(const float4*)(p + 4);
        float v[8] = {a.x, a.y, a.z, a.w, c.x, c.y, c.z, c.w};
        __nv_bfloat162 h[4];
#pragma unroll
        for (int e = 0; e < 4; e++) {
            float w0 = fmaxf(v[2*e]   - TE, 0.f) * inv_e - fmaxf(v[2*e]   - TI, 0.f) * inv_i;
            float w1 = fmaxf(v[2*e+1] - TE, 0.f) * inv_e - fmaxf(v[2*e+1] - TI, 0.f) * inv_i;
            h[e] = __floats2bfloat162_rn(w0, w1);
        }
        g_w2t[((size_t)(b * 16 + w) * 32 + t) * 32 + lane] = *(uint4*)h;
    }
}

// ---------------------------------------------------------------------------
// K_buildw: windowed bf16 l4w = lwe - normalized circle-masked l4c. grid = S2.
// ---------------------------------------------------------------------------
__global__ void K_buildw(const float* __restrict__ l4c, const float* __restrict__ lwe) {
    int row = blockIdx.x;
    int tid = threadIdx.x;
    int y = row >> 6, x = row & 63;
    float inv_m = 1.f / (g_smid[row] + 1e-11f);
    const float* l4crow = l4c + (size_t)row * S2;
    const float* lwerow = lwe + (size_t)row * S2;
    __nv_bfloat16* wrow = g_l4wh + (size_t)row * WN;
    for (int k = tid; k < WN; k += 256) {
        int dy = k / WW - WR;
        int dx = k % WW - WR;
        int yy = y + dy, xx = x + dx;
        float wv = 0.f;
        if ((unsigned)yy < S && (unsigned)xx < S) {
            int j = yy * S + xx;
            int d2 = dy * dy + dx * dx;
            float mid = (d2 <= 156) ? l4crow[j] * inv_m : 0.f;
            wv = lwerow[j] - mid;
        }
        wrow[k] = __float2bfloat16(wv);
    }
}

// ---------------------------------------------------------------------------
// K_aff: afferent drive per unit (one warp per unit).
// ---------------------------------------------------------------------------
__global__ void K_aff(const float* __restrict__ img, const int* __restrict__ grids,
                      const float* __restrict__ affw) {
    int unit = blockIdx.x * 8 + (threadIdx.x >> 5);
    int lane = threadIdx.x & 31;
    float a = 0.f;
    const int* g = grids + (size_t)unit * RFP * 2;
    const float* w = affw + (size_t)unit * RFP;
    for (int p = lane; p < RFP; p += 32) {
        a += img[g[p * 2 + 0] * INPUT + g[p * 2 + 1]] * w[p];
    }
    for (int o = 16; o; o >>= 1) a += __shfl_down_sync(0xffffffffu, a, o);
    if (lane == 0) g_aff[unit] = a;
}

__global__ void K_init() {
    int i = blockIdx.x * blockDim.x + threadIdx.x;
    if (i < S2) { g_cur[0][i] = 0.f; g_l4[0][i] = 0.f; }
    if (i == 0) g_bar = 0u;       // reset grid barrier every replay
}

// bf16x2 (packed) -> two floats, exact, on ALU pipe (shift / mask)
__device__ __forceinline__ void bf2f(unsigned p, float& lo, float& hi) {
    lo = __uint_as_float(p << 16);
    hi = __uint_as_float(p & 0xffff0000u);
}

// ---------------------------------------------------------------------------
// K_persist: all 50 settling steps. grid = 128 x 512 (16 warps/block).
// Block b owns rows [b*32, +32). Dense: warp w covers cols [w*256, +256),
// thread = row (x is a smem broadcast, weight loads 512B coalesced).
// ---------------------------------------------------------------------------
__global__ void __launch_bounds__(NTHR) K_persist(const float* __restrict__ thr,
                                                  const float* __restrict__ l4thr,
                                                  float* __restrict__ out) {
    __shared__ float4 scur4[S2 / 4];   // 16 KB
    __shared__ float  sl4[S2];         // 16 KB
    __shared__ float  red[16][32];     // 2 KB
    __shared__ float  swin[32];
    float* scur = (float*)scur4;
    int tid  = threadIdx.x;
    int warp = tid >> 5, lane = tid & 31;

    for (int it = 0; it < ITERS; it++) {
        int src = it & 1, dst = src ^ 1;

        // ---- stage state vectors into smem ----
        {
            const float4* c4  = (const float4*)g_cur[src];
            const float4* l4p = (const float4*)g_l4[src];
            float4* sl = (float4*)sl4;
            for (int i = tid; i < S2 / 4; i += NTHR) { scur4[i] = c4[i]; sl[i] = l4p[i]; }
        }
        __syncthreads();

        // ---- dense: W2 @ cur. warp w: cols [w*256, +256), 32 t-iters, MLP 8 ----
        {
            const uint4* wp = g_w2t + (size_t)(blockIdx.x * 16 + warp) * (32 * 32);
            float acc0 = 0.f, acc1 = 0.f;
#pragma unroll 8
            for (int t = 0; t < 32; t++) {
                uint4 wv = wp[t * 32 + lane];
                float4 xa = scur4[warp * 64 + 2 * t];       // broadcast
                float4 xb = scur4[warp * 64 + 2 * t + 1];   // broadcast
                float l0, h0, l1, h1, l2, h2, l3, h3;
                bf2f(wv.x, l0, h0); bf2f(wv.y, l1, h1);
                bf2f(wv.z, l2, h2); bf2f(wv.w, l3, h3);
                acc0 = fmaf(l0, xa.x, acc0); acc1 = fmaf(h0, xa.y, acc1);
                acc0 = fmaf(l1, xa.z, acc0); acc1 = fmaf(h1, xa.w, acc1);
                acc0 = fmaf(l2, xb.x, acc0); acc1 = fmaf(h2, xb.y, acc1);
                acc0 = fmaf(l3, xb.z, acc0); acc1 = fmaf(h3, xb.w, acc1);
            }
            red[warp][lane] = acc0 + acc1;
        }

        // ---- windowed: l4w @ l4 (warp per row, 2 rows per warp) ----
        for (int q = 0; q < 2; q++) {
            int rl = warp * 2 + q;
            int row = blockIdx.x * 32 + rl;
            int y = row >> 6, x = row & 63;
            const __nv_bfloat16* lw = g_l4wh + (size_t)row * WN;
            float a = 0.f;
#pragma unroll 4
            for (int k = lane; k < WN; k += 32) {
                int dy = k / WW - WR;
                int dx = k % WW - WR;
                int yy = min(max(y + dy, 0), S - 1);
                int xx = min(max(x + dx, 0), S - 1);
                a += __bfloat162float(lw[k]) * sl4[yy * S + xx];
            }
            for (int o = 16; o; o >>= 1) a += __shfl_down_sync(0xffffffffu, a, o);
            if (lane == 0) swin[rl] = a;
        }
        __syncthreads();

        // ---- final assembly: warp 0, one lane per row ----
        if (warp == 0) {
            int row = blockIdx.x * 32 + lane;
            float d = 0.f;
#pragma unroll
            for (int w = 0; w < 16; w++) d += red[w][lane];
            float l4_aff = 0.5f * (g_aff[row] + scur[row]);  // b == 1.0f exactly
            float l4n = tanhf(fmaxf(l4_aff + swin[lane] - l4thr[row], 0.f) * 2.0f);
            float curn = tanhf(fmaxf(l4n + d - thr[row], 0.f));
            g_l4[dst][row] = l4n;
            g_cur[dst][row] = curn;
            if (it == ITERS - 1) out[row] = curn;
        }

        // ---- grid barrier ----
        __threadfence();
        __syncthreads();
        if (tid == 0) {
            atomicAdd(&g_bar, 1u);
            unsigned target = (unsigned)(it + 1) * gridDim.x;
            while (*(volatile unsigned*)&g_bar < target) { }
            __threadfence();
        }
        __syncthreads();
    }
}

// ---------------------------------------------------------------------------
extern "C" void kernel_launch(void* const* d_in, const int* in_sizes, int n_in,
                              void* d_out, int out_size) {
    const float* img   = (const float*)d_in[0];
    const int*   grids = (const int*)d_in[1];
    const float* affw  = (const float*)d_in[2];
    const float* lc    = (const float*)d_in[3];
    const float* l4c   = (const float*)d_in[4];
    const float* lwe   = (const float*)d_in[5];
    const float* thr   = (const float*)d_in[7];
    const float* l4thr = (const float*)d_in[8];
    float* out = (float*)d_out;

    K_sums<<<S2, 256>>>(lc, l4c);
    K_build2<<<2048, 256>>>(lc);
    K_buildw<<<S2, 256>>>(l4c, lwe);
    K_aff<<<S2 / 8, 256>>>(img, grids, affw);
    K_init<<<(S2 + 255) / 256, 256>>>();
    K_persist<<<NBLK, NTHR>>>(thr, l4thr, out);
}